// round 17
// baseline (speedup 1.0000x reference)
#include <cuda_runtime.h>
#include <cuda_fp16.h>
#include <cstdint>

#define NN 50000
#define EE 1600000
#define CC 128
#define NG 128
#define SB 1024
#define NBK ((NN + SB - 1) / SB)   // 49

// ---- scratch (static device globals) ----
__device__ uint2  s_Ha [NN * 32];    // Hs ping (pre-scaled fp16 messages)
__device__ uint2  s_Hb [NN * 32];    // Hs pong
__device__ __half s_W1h[CC * CC];
__device__ __half s_W2h[CC * CC];
__device__ float  s_dinv[NN];
__device__ int    s_deg [NN];
__device__ int    s_rowptr[NN + 1];
__device__ int    s_cursor[NN];
__device__ int    s_csrc [EE];
__device__ int    s_bsum[64];
__device__ float  s_gacc[NG];

// ============ init: zero deg/gacc + convert W ============
__global__ void init_k(const float* __restrict__ W1, const float* __restrict__ W2) {
    int i = blockIdx.x * blockDim.x + threadIdx.x;
    if (i < NN) s_deg[i] = 0;
    if (i < NG) s_gacc[i] = 0.f;
    if (i < CC * CC) {
        s_W1h[i] = __float2half(W1[i]);
        s_W2h[i] = __float2half(W2[i]);
    }
}

__global__ void deg_k(const int* __restrict__ ei) {
    int t = blockIdx.x * blockDim.x + threadIdx.x;
    int e = t * 2;
    if (e + 1 < EE) {
        int2 d2 = *(const int2*)(ei + EE + e);
        int d0 = min(max(d2.x, 0), NN - 1);
        int d1 = min(max(d2.y, 0), NN - 1);
        atomicAdd(&s_deg[d0], 1);
        atomicAdd(&s_deg[d1], 1);
    } else if (e < EE) {
        int d0 = min(max(ei[EE + e], 0), NN - 1);
        atomicAdd(&s_deg[d0], 1);
    }
}

__global__ void scan1_k() {
    const int tid  = threadIdx.x;
    const int lane = tid & 31;
    const int wid  = tid >> 5;
    const int i    = blockIdx.x * SB + tid;
    int v = (i < NN) ? s_deg[i] : 0;
    int x = v;
    #pragma unroll
    for (int o = 1; o < 32; o <<= 1) {
        int t = __shfl_up_sync(0xffffffffu, x, o);
        if (lane >= o) x += t;
    }
    __shared__ int wsum[32];
    if (lane == 31) wsum[wid] = x;
    __syncthreads();
    if (wid == 0) {
        int s = wsum[lane];
        #pragma unroll
        for (int o = 1; o < 32; o <<= 1) {
            int t = __shfl_up_sync(0xffffffffu, s, o);
            if (lane >= o) s += t;
        }
        wsum[lane] = s;
    }
    __syncthreads();
    int incl = x + (wid ? wsum[wid - 1] : 0);
    if (i < NN) s_rowptr[i] = incl - v;
    if (tid == SB - 1) s_bsum[blockIdx.x] = incl;
}

__global__ void scan3_k() {
    const int tid = threadIdx.x;
    const int bid = blockIdx.x;
    __shared__ int sbase;
    if (tid < 32) {
        int v = 0;
        if (tid < bid) v = s_bsum[tid];
        if (tid + 32 < bid) v += s_bsum[tid + 32];
        #pragma unroll
        for (int o = 16; o; o >>= 1) v += __shfl_xor_sync(0xffffffffu, v, o);
        if (tid == 0) sbase = v;
    }
    __syncthreads();
    int base = sbase;
    int i = bid * SB + tid;
    if (i < NN) {
        int ex = s_rowptr[i] + base;
        s_rowptr[i] = ex;
        s_cursor[i] = ex;
        s_dinv[i]   = rsqrtf((float)s_deg[i] + 1.0f);
    }
    if (i == 0) s_rowptr[NN] = EE;
}

__global__ void build_k(const int* __restrict__ ei) {
    int e = blockIdx.x * blockDim.x + threadIdx.x;
    if (e >= EE) return;
    int src = ei[e];
    int dst = ei[EE + e];
    src = min(max(src, 0), NN - 1);
    dst = min(max(dst, 0), NN - 1);
    int slot = atomicAdd(&s_cursor[dst], 1);
    s_csrc[slot] = src;
}

// ============ shared pieces ============
__device__ __forceinline__ unsigned swz(unsigned row, unsigned col_half) {
    unsigned b = row * 256u + col_half * 2u;
    return b ^ ((row & 7u) << 4);
}

// gather: sum = HIN[node] + sum_e HIN[src_e]  (pure adds, pre-scaled msgs)
__device__ __forceinline__ float4 gather_sum(const uint2* __restrict__ HIN,
                                             int node, int lane) {
    uint2 hs = HIN[(size_t)node * 32 + lane];
    float2 h01 = __half22float2(*(__half2*)&hs.x);
    float2 h23 = __half22float2(*(__half2*)&hs.y);
    float4 acc = make_float4(h01.x, h01.y, h23.x, h23.y);

    const int beg = s_rowptr[node];
    const int end = s_rowptr[node + 1];
    int e = beg;
    for (; e + 4 <= end; e += 4) {
        int i0 = s_csrc[e], i1 = s_csrc[e+1], i2 = s_csrc[e+2], i3 = s_csrc[e+3];
        uint2 r0 = HIN[(size_t)i0 * 32 + lane];
        uint2 r1 = HIN[(size_t)i1 * 32 + lane];
        uint2 r2 = HIN[(size_t)i2 * 32 + lane];
        uint2 r3 = HIN[(size_t)i3 * 32 + lane];
        float2 a01, a23;
        a01 = __half22float2(*(__half2*)&r0.x); a23 = __half22float2(*(__half2*)&r0.y);
        acc.x += a01.x; acc.y += a01.y; acc.z += a23.x; acc.w += a23.y;
        a01 = __half22float2(*(__half2*)&r1.x); a23 = __half22float2(*(__half2*)&r1.y);
        acc.x += a01.x; acc.y += a01.y; acc.z += a23.x; acc.w += a23.y;
        a01 = __half22float2(*(__half2*)&r2.x); a23 = __half22float2(*(__half2*)&r2.y);
        acc.x += a01.x; acc.y += a01.y; acc.z += a23.x; acc.w += a23.y;
        a01 = __half22float2(*(__half2*)&r3.x); a23 = __half22float2(*(__half2*)&r3.y);
        acc.x += a01.x; acc.y += a01.y; acc.z += a23.x; acc.w += a23.y;
    }
    for (; e < end; e++) {
        uint2 r0 = HIN[(size_t)s_csrc[e] * 32 + lane];
        float2 a01 = __half22float2(*(__half2*)&r0.x);
        float2 a23 = __half22float2(*(__half2*)&r0.y);
        acc.x += a01.x; acc.y += a01.y; acc.z += a23.x; acc.w += a23.y;
    }
    return acc;
}

// MMA body: A (64x128 fp16) already in swizzled smem at sbA; W at sbW.
// Writes HOUT rows row0.. with dinv scaling.
__device__ __forceinline__ void mma_and_store(unsigned sbA, unsigned sbW,
                                              int row0, int tid,
                                              __half* __restrict__ HOUT) {
    const int warp   = tid >> 5;
    const int lane   = tid & 31;
    const int warp_m = warp & 3;
    const int warp_n = warp >> 2;
    const int rloc   = warp_m * 16;
    const int c0     = warp_n * 64;

    float d[8][4];
    #pragma unroll
    for (int i = 0; i < 8; i++)
        #pragma unroll
        for (int j = 0; j < 4; j++) d[i][j] = 0.f;

    const int fr = (lane & 7) + ((lane >> 3) & 1) * 8;
    const int fc = (lane >> 4) * 8;

    #pragma unroll
    for (int ks = 0; ks < 8; ks++) {
        const int k0 = ks * 16;
        unsigned a0, a1, a2, a3;
        {
            unsigned addrA = sbA + swz((unsigned)(rloc + fr), (unsigned)(k0 + fc));
            asm volatile("ldmatrix.sync.aligned.m8n8.x4.shared.b16 {%0,%1,%2,%3}, [%4];"
                         : "=r"(a0), "=r"(a1), "=r"(a2), "=r"(a3) : "r"(addrA));
        }
        #pragma unroll
        for (int q = 0; q < 4; q++) {
            int n0 = c0 + q * 16;
            unsigned b0, b1, b2, b3;
            unsigned addrB = sbW + swz((unsigned)(k0 + fr), (unsigned)(n0 + fc));
            asm volatile("ldmatrix.sync.aligned.m8n8.x4.trans.shared.b16 {%0,%1,%2,%3}, [%4];"
                         : "=r"(b0), "=r"(b1), "=r"(b2), "=r"(b3) : "r"(addrB));
            asm volatile("mma.sync.aligned.m16n8k16.row.col.f32.f16.f16.f32 "
                         "{%0,%1,%2,%3}, {%4,%5,%6,%7}, {%8,%9}, {%0,%1,%2,%3};"
                         : "+f"(d[q*2][0]), "+f"(d[q*2][1]), "+f"(d[q*2][2]), "+f"(d[q*2][3])
                         : "r"(a0), "r"(a1), "r"(a2), "r"(a3), "r"(b0), "r"(b1));
            asm volatile("mma.sync.aligned.m16n8k16.row.col.f32.f16.f16.f32 "
                         "{%0,%1,%2,%3}, {%4,%5,%6,%7}, {%8,%9}, {%0,%1,%2,%3};"
                         : "+f"(d[q*2+1][0]), "+f"(d[q*2+1][1]), "+f"(d[q*2+1][2]), "+f"(d[q*2+1][3])
                         : "r"(a0), "r"(a1), "r"(a2), "r"(a3), "r"(b2), "r"(b3));
        }
    }

    const int g  = lane >> 2;
    const int cq = (lane & 3) * 2;
    const int ra = row0 + rloc + g;
    const int rb = ra + 8;
    const float da = (ra < NN) ? s_dinv[ra] : 0.f;
    const float db = (rb < NN) ? s_dinv[rb] : 0.f;
    #pragma unroll
    for (int nt = 0; nt < 8; nt++) {
        int col = c0 + nt * 8 + cq;
        if (ra < NN) *(__half2*)(HOUT + (size_t)ra * CC + col) =
            __floats2half2_rn(d[nt][0] * da, d[nt][1] * da);
        if (rb < NN) *(__half2*)(HOUT + (size_t)rb * CC + col) =
            __floats2half2_rn(d[nt][2] * db, d[nt][3] * db);
    }
}

// W loader (2048 16B chunks, 256 threads)
__device__ __forceinline__ void load_w_smem(unsigned char* smem, int tid,
                                            const __half* __restrict__ Wh) {
    #pragma unroll
    for (int it = 0; it < 8; it++) {
        int idx = it * 256 + tid;
        int r   = idx >> 4;
        int c16 = idx & 15;
        uint4 o = *(const uint4*)(Wh + (size_t)r * CC + c16 * 8);
        *(uint4*)(smem + 16384 + swz((unsigned)r, (unsigned)(c16 * 8))) = o;
    }
}

// ============ layer-1 GEMM: Ha = (x @ W1) * dinv ============
__global__ void __launch_bounds__(256) gemm0_k(const float* __restrict__ X,
                                               const __half* __restrict__ Wh) {
    __shared__ __align__(16) unsigned char smem[49152];
    const unsigned sb  = (unsigned)__cvta_generic_to_shared(smem);
    const int tid  = threadIdx.x;
    const int row0 = blockIdx.x * 64;

    #pragma unroll
    for (int it = 0; it < 4; it++) {
        int idx = it * 256 + tid;
        int r   = idx >> 4;
        int c16 = idx & 15;
        int gr  = row0 + r;
        uint4 o;
        if (gr < NN) {
            const float4* p = (const float4*)(X + (size_t)gr * CC + c16 * 8);
            float4 f0 = p[0], f1 = p[1];
            __half2 h0 = __floats2half2_rn(f0.x, f0.y);
            __half2 h1 = __floats2half2_rn(f0.z, f0.w);
            __half2 h2 = __floats2half2_rn(f1.x, f1.y);
            __half2 h3 = __floats2half2_rn(f1.z, f1.w);
            o.x = *(unsigned*)&h0; o.y = *(unsigned*)&h1;
            o.z = *(unsigned*)&h2; o.w = *(unsigned*)&h3;
        } else {
            o = make_uint4(0u, 0u, 0u, 0u);
        }
        *(uint4*)(smem + swz((unsigned)r, (unsigned)(c16 * 8))) = o;
    }
    load_w_smem(smem, tid, Wh);
    __syncthreads();

    mma_and_store(sb, sb + 16384u, row0, tid, (__half*)s_Ha);
}

// ============ fused layer: agg(HIN) -> smem A -> GEMM(W2) -> HOUT ============
// SRC: 0 = read Ha write Hb; 1 = read Hb write Ha
template<int SRC>
__global__ void __launch_bounds__(256) fused_k(const __half* __restrict__ Wh,
                                               const float* __restrict__ bias) {
    __shared__ __align__(16) unsigned char smem[49152];
    const unsigned sb  = (unsigned)__cvta_generic_to_shared(smem);
    const int tid  = threadIdx.x;
    const int warp = tid >> 5;
    const int lane = tid & 31;
    const int row0 = blockIdx.x * 64;

    const uint2* HIN  = (SRC == 0) ? s_Ha : s_Hb;
    __half*      HOUT = (SRC == 0) ? (__half*)s_Hb : (__half*)s_Ha;

    // start W load first (overlaps with gather latency)
    load_w_smem(smem, tid, Wh);

    // gather phase: each warp computes 8 node rows into swizzled smem A
    const float bx = bias[lane * 4 + 0];
    const float by = bias[lane * 4 + 1];
    const float bz = bias[lane * 4 + 2];
    const float bw = bias[lane * 4 + 3];
    #pragma unroll
    for (int k = 0; k < 8; k++) {
        int lr   = warp * 8 + k;          // local row 0..63
        int node = row0 + lr;
        uint2 o = make_uint2(0u, 0u);
        if (node < NN) {
            float4 sum = gather_sum(HIN, node, lane);
            float di = s_dinv[node];
            float vx = fmaxf(fmaf(sum.x, di, bx), 0.f);
            float vy = fmaxf(fmaf(sum.y, di, by), 0.f);
            float vz = fmaxf(fmaf(sum.z, di, bz), 0.f);
            float vw = fmaxf(fmaf(sum.w, di, bw), 0.f);
            __half2 p0 = __floats2half2_rn(vx, vy);
            __half2 p1 = __floats2half2_rn(vz, vw);
            o.x = *(unsigned*)&p0;
            o.y = *(unsigned*)&p1;
        }
        unsigned addr = ((unsigned)lr * 256u + (unsigned)lane * 8u) ^ (((unsigned)lr & 7u) << 4);
        *(uint2*)(smem + addr) = o;
    }
    __syncthreads();

    mma_and_store(sb, sb + 16384u, row0, tid, HOUT);
}

// ============ FINAL aggregation from Hb: relu -> dot(Wfc) -> pool atomic ============
__global__ void agg_pool_k(const float* __restrict__ b,
                           const float* __restrict__ Wfc,
                           const int* __restrict__ batch) {
    int node = blockIdx.x * 8 + (threadIdx.x >> 5);
    int lane = threadIdx.x & 31;
    if (node >= NN) return;

    float4 sum = gather_sum(s_Hb, node, lane);
    float di = s_dinv[node];
    float vx = fmaf(sum.x, di, b[lane * 4 + 0]);
    float vy = fmaf(sum.y, di, b[lane * 4 + 1]);
    float vz = fmaf(sum.z, di, b[lane * 4 + 2]);
    float vw = fmaf(sum.w, di, b[lane * 4 + 3]);

    float4 w = *(const float4*)(Wfc + lane * 4);
    float dot = fmaxf(vx, 0.f) * w.x + fmaxf(vy, 0.f) * w.y
              + fmaxf(vz, 0.f) * w.z + fmaxf(vw, 0.f) * w.w;
    #pragma unroll
    for (int o = 16; o; o >>= 1) dot += __shfl_xor_sync(0xffffffffu, dot, o);
    if (lane == 0) atomicAdd(&s_gacc[batch[node]], dot);
}

// ============ finalize ============
__global__ void final_k(const int* __restrict__ batch,
                        const float* __restrict__ bfc,
                        float* __restrict__ out) {
    int g = threadIdx.x;
    if (g >= NG) return;
    int lo0 = 0, hi0 = NN;
    while (lo0 < hi0) { int m = (lo0 + hi0) >> 1; if (batch[m] < g) lo0 = m + 1; else hi0 = m; }
    int lo1 = lo0, hi1 = NN;
    while (lo1 < hi1) { int m = (lo1 + hi1) >> 1; if (batch[m] < g + 1) lo1 = m + 1; else hi1 = m; }
    float cnt = (float)(lo1 - lo0);
    out[g] = s_gacc[g] / fmaxf(cnt, 1.0f) + bfc[0];
}

extern "C" void kernel_launch(void* const* d_in, const int* in_sizes, int n_in,
                              void* d_out, int out_size) {
    const float* x   = (const float*)d_in[0];
    const int*   ei  = (const int*)d_in[1];    // int32 [2, E]
    const int*   bat = (const int*)d_in[2];    // int32 [N]
    const float* W1  = (const float*)d_in[3];
    const float* b1  = (const float*)d_in[4];
    const float* W2  = (const float*)d_in[5];
    const float* b2  = (const float*)d_in[6];
    const float* Wfc = (const float*)d_in[7];
    const float* bfc = (const float*)d_in[8];
    float*       out = (float*)d_out;

    __half *W1h, *W2h;
    cudaGetSymbolAddress((void**)&W1h, s_W1h);
    cudaGetSymbolAddress((void**)&W2h, s_W2h);

    const int T = 256;
    const int NB_N  = (NN + T - 1) / T;
    const int NB_E  = (EE + T - 1) / T;
    const int NB_E2 = (EE / 2 + T - 1) / T;
    const int GB    = (NN + 63) / 64;
    const int AB    = (NN + 7) / 8;

    // prologue
    init_k <<<NB_N, T>>>(W1, W2);
    deg_k  <<<NB_E2, T>>>(ei);
    scan1_k<<<NBK, SB>>>();
    scan3_k<<<NBK, SB>>>();
    build_k<<<NB_E, T>>>(ei);

    // layer 1 GEMM, then 3 fused (agg + GEMM) layers, then final agg+pool
    gemm0_k  <<<GB, 256>>>(x, W1h);        // x        -> Ha
    fused_k<0><<<GB, 256>>>(W2h, b1);      // agg1(Ha) -> gemm2 -> Hb
    fused_k<1><<<GB, 256>>>(W2h, b2);      // agg2(Hb) -> gemm3 -> Ha
    fused_k<0><<<GB, 256>>>(W2h, b2);      // agg3(Ha) -> gemm4 -> Hb
    agg_pool_k<<<AB, T>>>(b2, Wfc, bat);   // agg4(Hb) -> pooled dots

    final_k<<<1, NG>>>(bat, bfc, out);
}